// round 6
// baseline (speedup 1.0000x reference)
#include <cuda_runtime.h>
#include <math.h>

#define B_    128
#define T_    25
#define HID_  512
#define VOC_  10000
#define VGG_  4096
#define LOGITS_ELEMS (B_ * T_ * VOC_)
#define STATE_ELEMS  (2 * B_ * HID_)

typedef unsigned long long ull;

// ---------------- scratch (device globals; no allocation allowed) -----------
__device__ float g_X  [T_ * B_ * HID_];   // embedded tokens [t][b][e]
__device__ float g_s0 [B_ * HID_];        // layer-0 hidden
__device__ float g_s1 [B_ * HID_];        // layer-1 hidden
__device__ float g_gu [B_ * HID_];        // update gate
__device__ float g_grh[B_ * HID_];        // reset_gate * h
__device__ float g_seq[T_ * B_ * HID_];   // all layer-1 states [t][b][h]

// ---------------- packed f32x2 helpers --------------------------------------
__device__ __forceinline__ ull pk2(float x) {
    ull r; asm("mov.b64 %0, {%1, %1};" : "=l"(r) : "f"(x)); return r;
}
__device__ __forceinline__ void fma2(ull& c, ull a, ull b) {
    asm("fma.rn.f32x2 %0, %1, %2, %0;" : "+l"(c) : "l"(a), "l"(b));
}
__device__ __forceinline__ ull add2(ull a, ull b) {
    ull r; asm("add.rn.f32x2 %0, %1, %2;" : "=l"(r) : "l"(a), "l"(b)); return r;
}
__device__ __forceinline__ float2 upk(ull v) {
    float2 r; asm("mov.b64 {%0, %1}, %2;" : "=f"(r.x), "=f"(r.y) : "l"(v)); return r;
}
__device__ __forceinline__ float sigf(float z) { return 1.0f / (1.0f + expf(-z)); }

// ---------------- 32x32 tile GEMM, in-block split-K(2), 128 threads ---------
// Logical A = [A0 | A1] (each KHALF wide, row stride lda). Group g (64 thr)
// processes half g entirely. W row index = g*KHALF + k. Returns true for
// group 0, which then holds the fully reduced accumulators.
template <int KHALF>
__device__ __forceinline__ bool gemm32(const float* __restrict__ A0,
                                       const float* __restrict__ A1, int lda,
                                       const float* __restrict__ W, int ldw,
                                       int m0, int n0, ull acc[2][4])
{
    __shared__ __align__(16) float As[2][16][32];
    __shared__ __align__(16) float Bs[2][16][32];
    const int tid = threadIdx.x;
    const int g   = tid >> 6;
    const int lt  = tid & 63;
    const int ty  = lt >> 3;
    const int tx  = lt & 7;
    const float* A = g ? A1 : A0;

    #pragma unroll
    for (int i = 0; i < 2; i++)
        #pragma unroll
        for (int j = 0; j < 4; j++) acc[i][j] = 0ULL;

    for (int k0 = 0; k0 < KHALF; k0 += 16) {
        // A half-tile: 32 rows x 16 k = 128 float4, 2 per thread (transposed store)
        #pragma unroll
        for (int i = 0; i < 2; i++) {
            const int idx = lt * 2 + i;
            const int row = idx >> 2, kc = (idx & 3) << 2;
            const float4 v = *(const float4*)(A + (size_t)(m0 + row) * lda + k0 + kc);
            As[g][kc + 0][row] = v.x;
            As[g][kc + 1][row] = v.y;
            As[g][kc + 2][row] = v.z;
            As[g][kc + 3][row] = v.w;
        }
        // B half-tile: 16 k x 32 n = 128 float4, 2 per thread
        #pragma unroll
        for (int i = 0; i < 2; i++) {
            const int idx = lt * 2 + i;
            const int kr = idx >> 3, c4 = (idx & 7) << 2;
            const float4 v = *(const float4*)(W + (size_t)(g * KHALF + k0 + kr) * ldw + n0 + c4);
            *(float4*)&Bs[g][kr][c4] = v;
        }
        __syncthreads();
        #pragma unroll
        for (int kk = 0; kk < 16; kk++) {
            const ull* ar = (const ull*)As[g][kk];
            const ull a0 = ar[ty * 2];
            const ull a1 = ar[ty * 2 + 1];
            const float4 b = *(const float4*)&Bs[g][kk][tx * 4];
            const ull b0 = pk2(b.x), b1 = pk2(b.y), b2 = pk2(b.z), b3 = pk2(b.w);
            fma2(acc[0][0], a0, b0); fma2(acc[0][1], a0, b1);
            fma2(acc[0][2], a0, b2); fma2(acc[0][3], a0, b3);
            fma2(acc[1][0], a1, b0); fma2(acc[1][1], a1, b1);
            fma2(acc[1][2], a1, b2); fma2(acc[1][3], a1, b3);
        }
        __syncthreads();
    }

    // cross-group reduction: group 1 -> smem (overlay on As: 4096B exactly)
    ull* red = (ull*)&As[0][0][0];
    if (g) {
        #pragma unroll
        for (int i = 0; i < 2; i++)
            #pragma unroll
            for (int j = 0; j < 4; j++) red[lt * 8 + i * 4 + j] = acc[i][j];
    }
    __syncthreads();
    if (!g) {
        #pragma unroll
        for (int i = 0; i < 2; i++)
            #pragma unroll
            for (int j = 0; j < 4; j++)
                acc[i][j] = add2(acc[i][j], red[lt * 8 + i * 4 + j]);
    }
    return g == 0;
}

// ---------------- GRU gates: [x|h] @ (Wu ‖ Wr), fused u+r -------------------
__global__ __launch_bounds__(128) void k_gates(
    const float* __restrict__ x, const float* __restrict__ h,
    const float* __restrict__ Wu, const float* __restrict__ bu,
    const float* __restrict__ Wr, const float* __restrict__ br)
{
    const int m0 = blockIdx.x * 32;
    const int nc = blockIdx.y * 32;          // combined 0..1023
    const bool isU = nc < HID_;
    const float* W    = isU ? Wu : Wr;
    const float* bias = isU ? bu : br;
    const int n0 = isU ? nc : nc - HID_;

    ull acc[2][4];
    if (!gemm32<HID_>(x, h, HID_, W, HID_, m0, n0, acc)) return;

    const int lt = threadIdx.x & 63;
    const int ty = lt >> 3, tx = lt & 7;
    #pragma unroll
    for (int i = 0; i < 2; i++)
        #pragma unroll
        for (int j = 0; j < 4; j++) {
            const float2 v = upk(acc[i][j]);
            const int r = m0 + ty * 4 + i * 2;
            const int c = n0 + tx * 4 + j;
            const float bb = bias[c];
            const float u0 = sigf(v.x + bb);
            const float u1 = sigf(v.y + bb);
            if (isU) {
                g_gu[r * HID_ + c]       = u0;
                g_gu[(r + 1) * HID_ + c] = u1;
            } else {
                g_grh[r * HID_ + c]       = u0 * h[r * HID_ + c];
                g_grh[(r + 1) * HID_ + c] = u1 * h[(r + 1) * HID_ + c];
            }
        }
}

// ---------------- GRU candidate + state update ------------------------------
__global__ __launch_bounds__(128) void k_cand(
    const float* __restrict__ x,
    const float* __restrict__ Wc, const float* __restrict__ bc,
    float* __restrict__ h, float* __restrict__ seq)
{
    const int m0 = blockIdx.x * 32;
    const int n0 = blockIdx.y * 32;

    ull acc[2][4];
    if (!gemm32<HID_>(x, g_grh, HID_, Wc, HID_, m0, n0, acc)) return;

    const int lt = threadIdx.x & 63;
    const int ty = lt >> 3, tx = lt & 7;
    #pragma unroll
    for (int i = 0; i < 2; i++)
        #pragma unroll
        for (int j = 0; j < 4; j++) {
            const float2 v = upk(acc[i][j]);
            const int r = m0 + ty * 4 + i * 2;
            const int c = n0 + tx * 4 + j;
            const float bb = bc[c];
            #pragma unroll
            for (int s = 0; s < 2; s++) {
                const int rr = r + s;
                const float hh = tanhf((s ? v.y : v.x) + bb);
                const float gg = g_gu[rr * HID_ + c];
                const float hn = gg * h[rr * HID_ + c] + (1.0f - gg) * hh;
                h[rr * HID_ + c] = hn;
                if (seq) seq[rr * HID_ + c] = hn;
            }
        }
}

// ---------------- h0 = tanh(vgg @ W_in + b_in), broadcast to s0,s1 ----------
__global__ __launch_bounds__(128) void k_h0(
    const float* __restrict__ vgg, const float* __restrict__ W_in,
    const float* __restrict__ b_in)
{
    const int m0 = blockIdx.x * 32;
    const int n0 = blockIdx.y * 32;

    ull acc[2][4];
    if (!gemm32<(VGG_ / 2)>(vgg, vgg + VGG_ / 2, VGG_, W_in, HID_, m0, n0, acc)) return;

    const int lt = threadIdx.x & 63;
    const int ty = lt >> 3, tx = lt & 7;
    #pragma unroll
    for (int i = 0; i < 2; i++)
        #pragma unroll
        for (int j = 0; j < 4; j++) {
            const float2 v = upk(acc[i][j]);
            const int r = m0 + ty * 4 + i * 2;
            const int c = n0 + tx * 4 + j;
            const float bb = b_in[c];
            const float v0 = tanhf(v.x + bb);
            const float v1 = tanhf(v.y + bb);
            g_s0[r * HID_ + c] = v0;       g_s1[r * HID_ + c] = v0;
            g_s0[(r + 1) * HID_ + c] = v1; g_s1[(r + 1) * HID_ + c] = v1;
        }
}

// ---------------- embedding gather ------------------------------------------
__global__ void k_embed(const float* __restrict__ emb, const int* __restrict__ tok)
{
    const int i = blockIdx.x * 256 + threadIdx.x;      // float4 index
    if (i >= T_ * B_ * (HID_ / 4)) return;
    const int e4 = i & 127;
    const int tb = i >> 7;
    const int t = tb / B_;
    const int b = tb - t * B_;
    const int tk = tok[b * T_ + t];
    ((float4*)g_X)[i] = ((const float4*)emb)[(size_t)tk * (HID_ / 4) + e4];
}

// ---------------- logits: g_seq[3200,512] @ W_out[512,10000] + b_out --------
// 64x64 tile, 256 threads, each 4 rows (2 f32x2 pairs) x 4 cols
__global__ __launch_bounds__(256) void k_logits(
    const float* __restrict__ Wo, const float* __restrict__ bo,
    float* __restrict__ out)
{
    __shared__ __align__(16) float As[16][64];
    __shared__ __align__(16) float Bs[16][64];
    const int tid = threadIdx.x;
    const int m0 = blockIdx.x * 64;
    const int n0 = blockIdx.y * 64;
    const int ty = tid >> 4, tx = tid & 15;

    ull acc[2][4];
    #pragma unroll
    for (int i = 0; i < 2; i++)
        #pragma unroll
        for (int j = 0; j < 4; j++) acc[i][j] = 0ULL;

    for (int k0 = 0; k0 < HID_; k0 += 16) {
        {   // A tile: 64x16 = 256 float4, 1 per thread (transposed store)
            const int row = tid >> 2, kc = (tid & 3) << 2;
            const float4 v = *(const float4*)(g_seq + (size_t)(m0 + row) * HID_ + k0 + kc);
            As[kc + 0][row] = v.x; As[kc + 1][row] = v.y;
            As[kc + 2][row] = v.z; As[kc + 3][row] = v.w;
        }
        {   // B tile: 16x64 = 256 float4, 1 per thread (N-bounds guarded)
            const int kr = tid >> 4, c4 = (tid & 15) << 2;
            const int gc = n0 + c4;
            const float* Wr = Wo + (size_t)(k0 + kr) * VOC_;
            float4 v;
            if (gc + 3 < VOC_) {
                v = *(const float4*)(Wr + gc);
            } else {
                v.x = (gc + 0 < VOC_) ? Wr[gc + 0] : 0.0f;
                v.y = (gc + 1 < VOC_) ? Wr[gc + 1] : 0.0f;
                v.z = (gc + 2 < VOC_) ? Wr[gc + 2] : 0.0f;
                v.w = (gc + 3 < VOC_) ? Wr[gc + 3] : 0.0f;
            }
            *(float4*)&Bs[kr][c4] = v;
        }
        __syncthreads();
        #pragma unroll
        for (int kk = 0; kk < 16; kk++) {
            const ull* ar = (const ull*)As[kk];
            const ull a0 = ar[ty * 2];
            const ull a1 = ar[ty * 2 + 1];
            const float4 b = *(const float4*)&Bs[kk][tx * 4];
            const ull b0 = pk2(b.x), b1 = pk2(b.y), b2 = pk2(b.z), b3 = pk2(b.w);
            fma2(acc[0][0], a0, b0); fma2(acc[0][1], a0, b1);
            fma2(acc[0][2], a0, b2); fma2(acc[0][3], a0, b3);
            fma2(acc[1][0], a1, b0); fma2(acc[1][1], a1, b1);
            fma2(acc[1][2], a1, b2); fma2(acc[1][3], a1, b3);
        }
        __syncthreads();
    }

    // epilogue: seq row r = t*B + b  ->  out row b*T + t
    #pragma unroll
    for (int i = 0; i < 2; i++)
        #pragma unroll
        for (int j = 0; j < 4; j++) {
            const float2 v = upk(acc[i][j]);
            const int c = n0 + tx * 4 + j;
            if (c >= VOC_) continue;
            const float bb = bo[c];
            #pragma unroll
            for (int s = 0; s < 2; s++) {
                const int r = m0 + ty * 4 + i * 2 + s;
                const int t = r / B_;
                const int b = r - t * B_;
                out[(size_t)(b * T_ + t) * VOC_ + c] = (s ? v.y : v.x) + bb;
            }
        }
}

// ---------------- final state copy ------------------------------------------
__global__ void k_state(float* __restrict__ out)
{
    const int i = blockIdx.x * 256 + threadIdx.x;
    if (i >= B_ * HID_) return;
    out[LOGITS_ELEMS + i]             = g_s0[i];
    out[LOGITS_ELEMS + B_ * HID_ + i] = g_s1[i];
}

// ---------------- launch -----------------------------------------------------
extern "C" void kernel_launch(void* const* d_in, const int* in_sizes, int n_in,
                              void* d_out, int out_size)
{
    const float* vgg  = (const float*)d_in[0];
    const int*   tok  = (const int*)  d_in[1];
    // d_in[2] = is_train (unused by the reference computation)
    const float* emb  = (const float*)d_in[3];
    const float* W_in = (const float*)d_in[4];
    const float* b_in = (const float*)d_in[5];
    const float* Wu0  = (const float*)d_in[6];
    const float* bu0  = (const float*)d_in[7];
    const float* Wr0  = (const float*)d_in[8];
    const float* br0  = (const float*)d_in[9];
    const float* Wc0  = (const float*)d_in[10];
    const float* bc0  = (const float*)d_in[11];
    const float* Wu1  = (const float*)d_in[12];
    const float* bu1  = (const float*)d_in[13];
    const float* Wr1  = (const float*)d_in[14];
    const float* br1  = (const float*)d_in[15];
    const float* Wc1  = (const float*)d_in[16];
    const float* bc1  = (const float*)d_in[17];
    const float* Wo   = (const float*)d_in[18];
    const float* bo   = (const float*)d_in[19];
    float* out = (float*)d_out;

    void *pX, *pS0, *pS1, *pSeq;
    cudaGetSymbolAddress(&pX,  g_X);
    cudaGetSymbolAddress(&pS0, g_s0);
    cudaGetSymbolAddress(&pS1, g_s1);
    cudaGetSymbolAddress(&pSeq, g_seq);
    float* X   = (float*)pX;
    float* s0  = (float*)pS0;
    float* s1  = (float*)pS1;
    float* seq = (float*)pSeq;

    k_embed<<<(T_ * B_ * (HID_ / 4) + 255) / 256, 256>>>(emb, tok);
    k_h0<<<dim3(4, 16), 128>>>(vgg, W_in, b_in);

    const dim3 gGates(4, 32);   // combined u|r -> N=1024
    const dim3 gCand (4, 16);   // N=512
    for (int t = 0; t < T_; t++) {
        const float* xt = X + (size_t)t * B_ * HID_;
        k_gates<<<gGates, 128>>>(xt, s0, Wu0, bu0, Wr0, br0);
        k_cand <<<gCand, 128>>>(xt, Wc0, bc0, s0, (float*)0);
        k_gates<<<gGates, 128>>>(s0, s1, Wu1, bu1, Wr1, br1);
        k_cand <<<gCand, 128>>>(s0, Wc1, bc1, s1, seq + (size_t)t * B_ * HID_);
    }

    k_logits<<<dim3((B_ * T_) / 64, (VOC_ + 63) / 64), 256>>>(Wo, bo, out);
    if (out_size >= LOGITS_ELEMS + STATE_ELEMS)
        k_state<<<(B_ * HID_ + 255) / 256, 256>>>(out);
}

// round 7
// speedup vs baseline: 1.0465x; 1.0465x over previous
#include <cuda_runtime.h>
#include <math.h>

#define B_    128
#define T_    25
#define HID_  512
#define VOC_  10000
#define VGG_  4096
#define MB_   (T_ * B_)                 // 3200 rows of X / seq
#define LOGITS_ELEMS (B_ * T_ * VOC_)
#define STATE_ELEMS  (2 * B_ * HID_)

typedef unsigned long long ull;

// ---------------- scratch (device globals; no allocation allowed) -----------
__device__ float g_X  [MB_ * HID_];       // embedded tokens [t*B+b][e]
__device__ float g_P  [3 * MB_ * HID_];   // precomputed x-projections (u,r,c)
__device__ float g_s0 [B_ * HID_];        // layer-0 hidden
__device__ float g_s1 [B_ * HID_];        // layer-1 hidden
__device__ float g_gu [B_ * HID_];        // update gate
__device__ float g_grh[B_ * HID_];        // reset_gate * h
__device__ float g_seq[MB_ * HID_];       // all layer-1 states

// ---------------- packed f32x2 helpers --------------------------------------
__device__ __forceinline__ ull pk2(float x) {
    ull r; asm("mov.b64 %0, {%1, %1};" : "=l"(r) : "f"(x)); return r;
}
__device__ __forceinline__ void fma2(ull& c, ull a, ull b) {
    asm("fma.rn.f32x2 %0, %1, %2, %0;" : "+l"(c) : "l"(a), "l"(b));
}
__device__ __forceinline__ ull add2(ull a, ull b) {
    ull r; asm("add.rn.f32x2 %0, %1, %2;" : "=l"(r) : "l"(a), "l"(b)); return r;
}
__device__ __forceinline__ float2 upk(ull v) {
    float2 r; asm("mov.b64 {%0, %1}, %2;" : "=f"(r.x), "=f"(r.y) : "l"(v)); return r;
}
__device__ __forceinline__ float sigf(float z) { return 1.0f / (1.0f + expf(-z)); }

// ============================================================================
// Recurrence GEMM core: 32x32 tile, 256 threads = 8 k-groups x 32 lanes.
// Logical A = [A0 | A1] split at ka0. Group g handles K-slice
// [g*KG, (g+1)*KG), KG = NCHUNK*16, total K = 8*KG. Micro-tile per lane:
// 4 rows x 8 cols; B read as packed f32x2 directly from smem, A scalar
// broadcast via pk2. Register prefetch hides gmem latency. Returns true
// for group 0 which holds the reduced accumulators.
// ============================================================================
template <int NCHUNK>
__device__ __forceinline__ bool rec_gemm(
    const float* __restrict__ A0, int lda0, int ka0,
    const float* __restrict__ A1, int lda1,
    const float* __restrict__ W,  int ldw,
    int m0, int n0, ull acc[4][4])
{
    __shared__ __align__(16) float As[8][16][32];
    __shared__ __align__(16) float Bs[8][16][32];
    const int tid  = threadIdx.x;
    const int g    = tid >> 5;
    const int lane = tid & 31;
    const int ty   = lane >> 2;      // 0..7 -> rows 4ty..4ty+3
    const int tx   = lane & 3;       // 0..3 -> cols 8tx..8tx+7
    constexpr int KG = NCHUNK * 16;

    #pragma unroll
    for (int r = 0; r < 4; r++)
        #pragma unroll
        for (int c = 0; c < 4; c++) acc[r][c] = 0ULL;

    float4 pa[4], pb[4];
    auto loadc = [&](int c) {
        const int kb = g * KG + c * 16;
        const float* A; int lda, ka;
        if (kb < ka0) { A = A0; lda = lda0; ka = kb; }
        else          { A = A1; lda = lda1; ka = kb - ka0; }
        #pragma unroll
        for (int i = 0; i < 4; i++) {
            const int idx = lane * 4 + i;
            pa[i] = *(const float4*)(A + (size_t)(m0 + (idx >> 2)) * lda + ka + ((idx & 3) << 2));
            pb[i] = *(const float4*)(W + (size_t)(kb + (idx >> 3)) * ldw + n0 + ((idx & 7) << 2));
        }
    };

    loadc(0);
    for (int c = 0; c < NCHUNK; c++) {
        #pragma unroll
        for (int i = 0; i < 4; i++) {
            const int idx = lane * 4 + i;
            const int row = idx >> 2, kc = (idx & 3) << 2;
            As[g][kc + 0][row] = pa[i].x;
            As[g][kc + 1][row] = pa[i].y;
            As[g][kc + 2][row] = pa[i].z;
            As[g][kc + 3][row] = pa[i].w;
            *(float4*)&Bs[g][idx >> 3][(idx & 7) << 2] = pb[i];
        }
        __syncthreads();
        if (c + 1 < NCHUNK) loadc(c + 1);
        #pragma unroll
        for (int kk = 0; kk < 16; kk++) {
            const float4 a = *(const float4*)&As[g][kk][ty << 2];
            const ull* br = (const ull*)Bs[g][kk];
            const ull b0 = br[tx * 4 + 0], b1 = br[tx * 4 + 1];
            const ull b2 = br[tx * 4 + 2], b3 = br[tx * 4 + 3];
            ull ar;
            ar = pk2(a.x);
            fma2(acc[0][0], ar, b0); fma2(acc[0][1], ar, b1);
            fma2(acc[0][2], ar, b2); fma2(acc[0][3], ar, b3);
            ar = pk2(a.y);
            fma2(acc[1][0], ar, b0); fma2(acc[1][1], ar, b1);
            fma2(acc[1][2], ar, b2); fma2(acc[1][3], ar, b3);
            ar = pk2(a.z);
            fma2(acc[2][0], ar, b0); fma2(acc[2][1], ar, b1);
            fma2(acc[2][2], ar, b2); fma2(acc[2][3], ar, b3);
            ar = pk2(a.w);
            fma2(acc[3][0], ar, b0); fma2(acc[3][1], ar, b1);
            fma2(acc[3][2], ar, b2); fma2(acc[3][3], ar, b3);
        }
        __syncthreads();
    }

    // tree reduction over the 8 groups (overlay on As: 16KB needed, 16KB avail)
    ull* red = (ull*)&As[0][0][0];
    #pragma unroll
    for (int off = 4; off >= 1; off >>= 1) {
        if (g >= off && g < 2 * off) {
            ull* p = red + (size_t)(((g - off) << 5) + lane) * 16;
            #pragma unroll
            for (int r = 0; r < 4; r++)
                #pragma unroll
                for (int c = 0; c < 4; c++) p[r * 4 + c] = acc[r][c];
        }
        __syncthreads();
        if (g < off) {
            const ull* p = red + (size_t)((g << 5) + lane) * 16;
            #pragma unroll
            for (int r = 0; r < 4; r++)
                #pragma unroll
                for (int c = 0; c < 4; c++) acc[r][c] = add2(acc[r][c], p[r * 4 + c]);
        }
        __syncthreads();
    }
    return g == 0;
}

// ---------------- GRU gates (u and r fused via blockIdx.y) ------------------
template <int NCHUNK>
__global__ __launch_bounds__(256) void k_gates(
    const float* __restrict__ A0, const float* __restrict__ A1, int ka0,
    const float* __restrict__ Wu, const float* __restrict__ bu,
    const float* __restrict__ Wr, const float* __restrict__ br,
    const float* __restrict__ Pu, const float* __restrict__ Pr,
    const float* __restrict__ h)
{
    const int m0 = blockIdx.x * 32;
    const int nc = blockIdx.y * 32;
    const bool isU = nc < HID_;
    const float* W    = isU ? Wu : Wr;
    const float* bias = isU ? bu : br;
    const float* P    = isU ? Pu : Pr;
    const int n0 = isU ? nc : nc - HID_;

    ull acc[4][4];
    if (!rec_gemm<NCHUNK>(A0, HID_, ka0, A1, HID_, W, HID_, m0, n0, acc)) return;

    const int lane = threadIdx.x & 31;
    const int ty = lane >> 2, tx = lane & 3;
    #pragma unroll
    for (int r = 0; r < 4; r++) {
        const int row = m0 + (ty << 2) + r;
        #pragma unroll
        for (int cp = 0; cp < 4; cp++) {
            const float2 v = upk(acc[r][cp]);
            const float vv[2] = {v.x, v.y};
            #pragma unroll
            for (int s = 0; s < 2; s++) {
                const int c = n0 + (tx << 3) + (cp << 1) + s;
                float val = vv[s] + bias[c];
                if (P) val += P[row * HID_ + c];
                const float sg = sigf(val);
                if (isU) g_gu[row * HID_ + c] = sg;
                else     g_grh[row * HID_ + c] = sg * h[row * HID_ + c];
            }
        }
    }
}

// ---------------- GRU candidate + state update ------------------------------
template <int NCHUNK>
__global__ __launch_bounds__(256) void k_cand(
    const float* __restrict__ A0, const float* __restrict__ A1, int ka0,
    const float* __restrict__ Wc, const float* __restrict__ bc,
    const float* __restrict__ Pc,
    float* __restrict__ h, float* __restrict__ seq)
{
    const int m0 = blockIdx.x * 32;
    const int n0 = blockIdx.y * 32;

    ull acc[4][4];
    if (!rec_gemm<NCHUNK>(A0, HID_, ka0, A1, HID_, Wc, HID_, m0, n0, acc)) return;

    const int lane = threadIdx.x & 31;
    const int ty = lane >> 2, tx = lane & 3;
    #pragma unroll
    for (int r = 0; r < 4; r++) {
        const int row = m0 + (ty << 2) + r;
        #pragma unroll
        for (int cp = 0; cp < 4; cp++) {
            const float2 v = upk(acc[r][cp]);
            const float vv[2] = {v.x, v.y};
            #pragma unroll
            for (int s = 0; s < 2; s++) {
                const int c = n0 + (tx << 3) + (cp << 1) + s;
                float val = vv[s] + bc[c];
                if (Pc) val += Pc[row * HID_ + c];
                const float hh = tanhf(val);
                const float gg = g_gu[row * HID_ + c];
                const float hn = gg * h[row * HID_ + c] + (1.0f - gg) * hh;
                h[row * HID_ + c] = hn;
                if (seq) seq[row * HID_ + c] = hn;
            }
        }
    }
}

// ---------------- h0 = tanh(vgg @ W_in + b_in) ------------------------------
__global__ __launch_bounds__(256) void k_h0(
    const float* __restrict__ vgg, const float* __restrict__ W_in,
    const float* __restrict__ b_in)
{
    const int m0 = blockIdx.x * 32;
    const int n0 = blockIdx.y * 32;

    ull acc[4][4];
    if (!rec_gemm<32>(vgg, VGG_, VGG_, vgg, VGG_, W_in, HID_, m0, n0, acc)) return;

    const int lane = threadIdx.x & 31;
    const int ty = lane >> 2, tx = lane & 3;
    #pragma unroll
    for (int r = 0; r < 4; r++) {
        const int row = m0 + (ty << 2) + r;
        #pragma unroll
        for (int cp = 0; cp < 4; cp++) {
            const float2 v = upk(acc[r][cp]);
            const float vv[2] = {v.x, v.y};
            #pragma unroll
            for (int s = 0; s < 2; s++) {
                const int c = n0 + (tx << 3) + (cp << 1) + s;
                const float t = tanhf(vv[s] + b_in[c]);
                g_s0[row * HID_ + c] = t;
                g_s1[row * HID_ + c] = t;
            }
        }
    }
}

// ============================================================================
// Big parallel GEMM core: 64x64 tile, 128 threads, micro-tile 4x8,
// register-prefetch double buffering. Used by logits and precompute.
// K fixed at 512.
// ============================================================================
template <bool GUARD>
__device__ __forceinline__ void big_gemm(
    const float* __restrict__ A, int lda,
    const float* __restrict__ W, int ldw, int nmax,
    int m0, int n0, ull acc[4][4])
{
    __shared__ __align__(16) float As[16][64];
    __shared__ __align__(16) float Bs[16][64];
    const int tid = threadIdx.x;
    const int ty = tid >> 3, tx = tid & 7;

    #pragma unroll
    for (int r = 0; r < 4; r++)
        #pragma unroll
        for (int c = 0; c < 4; c++) acc[r][c] = 0ULL;

    float4 pa[2], pb[2];
    auto loadc = [&](int k0) {
        #pragma unroll
        for (int i = 0; i < 2; i++) {
            const int idx = tid * 2 + i;
            pa[i] = *(const float4*)(A + (size_t)(m0 + (idx >> 2)) * lda + k0 + ((idx & 3) << 2));
            const int kr = idx >> 4, c4 = (idx & 15) << 2;
            const int gc = n0 + c4;
            const float* Wr = W + (size_t)(k0 + kr) * ldw;
            if (!GUARD || gc + 3 < nmax) {
                pb[i] = *(const float4*)(Wr + gc);
            } else {
                pb[i].x = (gc + 0 < nmax) ? Wr[gc + 0] : 0.0f;
                pb[i].y = (gc + 1 < nmax) ? Wr[gc + 1] : 0.0f;
                pb[i].z = (gc + 2 < nmax) ? Wr[gc + 2] : 0.0f;
                pb[i].w = (gc + 3 < nmax) ? Wr[gc + 3] : 0.0f;
            }
        }
    };

    loadc(0);
    for (int k0 = 0; k0 < HID_; k0 += 16) {
        #pragma unroll
        for (int i = 0; i < 2; i++) {
            const int idx = tid * 2 + i;
            const int row = idx >> 2, kc = (idx & 3) << 2;
            As[kc + 0][row] = pa[i].x;
            As[kc + 1][row] = pa[i].y;
            As[kc + 2][row] = pa[i].z;
            As[kc + 3][row] = pa[i].w;
            *(float4*)&Bs[idx >> 4][(idx & 15) << 2] = pb[i];
        }
        __syncthreads();
        if (k0 + 16 < HID_) loadc(k0 + 16);
        #pragma unroll
        for (int kk = 0; kk < 16; kk++) {
            const float4 a = *(const float4*)&As[kk][ty << 2];
            const ull* br = (const ull*)Bs[kk];
            const ull b0 = br[tx * 4 + 0], b1 = br[tx * 4 + 1];
            const ull b2 = br[tx * 4 + 2], b3 = br[tx * 4 + 3];
            ull ar;
            ar = pk2(a.x);
            fma2(acc[0][0], ar, b0); fma2(acc[0][1], ar, b1);
            fma2(acc[0][2], ar, b2); fma2(acc[0][3], ar, b3);
            ar = pk2(a.y);
            fma2(acc[1][0], ar, b0); fma2(acc[1][1], ar, b1);
            fma2(acc[1][2], ar, b2); fma2(acc[1][3], ar, b3);
            ar = pk2(a.z);
            fma2(acc[2][0], ar, b0); fma2(acc[2][1], ar, b1);
            fma2(acc[2][2], ar, b2); fma2(acc[2][3], ar, b3);
            ar = pk2(a.w);
            fma2(acc[3][0], ar, b0); fma2(acc[3][1], ar, b1);
            fma2(acc[3][2], ar, b2); fma2(acc[3][3], ar, b3);
        }
        __syncthreads();
    }
}

// ---------------- precompute: P[z] = X @ Wz[0:512]  (z = u0, r0, c0) --------
__global__ __launch_bounds__(128) void k_prec(
    const float* __restrict__ Wu0, const float* __restrict__ Wr0,
    const float* __restrict__ Wc0)
{
    const int z = blockIdx.z;
    const float* W = (z == 0) ? Wu0 : ((z == 1) ? Wr0 : Wc0);
    float* outp = g_P + (size_t)z * MB_ * HID_;
    const int m0 = blockIdx.x * 64;
    const int n0 = blockIdx.y * 64;

    ull acc[4][4];
    big_gemm<false>(g_X, HID_, W, HID_, HID_, m0, n0, acc);

    const int tid = threadIdx.x;
    const int ty = tid >> 3, tx = tid & 7;
    #pragma unroll
    for (int r = 0; r < 4; r++) {
        const int row = m0 + (ty << 2) + r;
        #pragma unroll
        for (int cp = 0; cp < 4; cp++) {
            const float2 v = upk(acc[r][cp]);
            const int c = n0 + (tx << 3) + (cp << 1);
            outp[(size_t)row * HID_ + c]     = v.x;
            outp[(size_t)row * HID_ + c + 1] = v.y;
        }
    }
}

// ---------------- logits: g_seq[3200,512] @ W_out[512,10000] + b_out --------
__global__ __launch_bounds__(128) void k_logits(
    const float* __restrict__ Wo, const float* __restrict__ bo,
    float* __restrict__ out)
{
    const int m0 = blockIdx.x * 64;
    const int n0 = blockIdx.y * 64;

    ull acc[4][4];
    big_gemm<true>(g_seq, HID_, Wo, VOC_, VOC_, m0, n0, acc);

    const int tid = threadIdx.x;
    const int ty = tid >> 3, tx = tid & 7;
    #pragma unroll
    for (int r = 0; r < 4; r++) {
        const int row = m0 + (ty << 2) + r;   // row = t*B + b
        const int tt = row >> 7;
        const int bb = row & (B_ - 1);
        const size_t obase = (size_t)(bb * T_ + tt) * VOC_;
        #pragma unroll
        for (int cp = 0; cp < 4; cp++) {
            const float2 v = upk(acc[r][cp]);
            const float vv[2] = {v.x, v.y};
            #pragma unroll
            for (int s = 0; s < 2; s++) {
                const int c = n0 + (tx << 3) + (cp << 1) + s;
                if (c < VOC_) out[obase + c] = vv[s] + bo[c];
            }
        }
    }
}

// ---------------- embedding gather ------------------------------------------
__global__ void k_embed(const float* __restrict__ emb, const int* __restrict__ tok)
{
    const int i = blockIdx.x * 256 + threadIdx.x;      // float4 index
    if (i >= MB_ * (HID_ / 4)) return;
    const int e4 = i & 127;
    const int tb = i >> 7;                             // t*B + b
    const int t = tb >> 7;
    const int b = tb & (B_ - 1);
    const int tk = tok[b * T_ + t];
    ((float4*)g_X)[i] = ((const float4*)emb)[(size_t)tk * (HID_ / 4) + e4];
}

// ---------------- final state copy ------------------------------------------
__global__ void k_state(float* __restrict__ out)
{
    const int i = blockIdx.x * 256 + threadIdx.x;
    if (i >= B_ * HID_) return;
    out[LOGITS_ELEMS + i]             = g_s0[i];
    out[LOGITS_ELEMS + B_ * HID_ + i] = g_s1[i];
}

// ---------------- launch -----------------------------------------------------
extern "C" void kernel_launch(void* const* d_in, const int* in_sizes, int n_in,
                              void* d_out, int out_size)
{
    const float* vgg  = (const float*)d_in[0];
    const int*   tok  = (const int*)  d_in[1];
    // d_in[2] = is_train (unused)
    const float* emb  = (const float*)d_in[3];
    const float* W_in = (const float*)d_in[4];
    const float* b_in = (const float*)d_in[5];
    const float* Wu0  = (const float*)d_in[6];
    const float* bu0  = (const float*)d_in[7];
    const float* Wr0  = (const float*)d_in[8];
    const float* br0  = (const float*)d_in[9];
    const float* Wc0  = (const float*)d_in[10];
    const float* bc0  = (const float*)d_in[11];
    const float* Wu1  = (const float*)d_in[12];
    const float* bu1  = (const float*)d_in[13];
    const float* Wr1  = (const float*)d_in[14];
    const float* br1  = (const float*)d_in[15];
    const float* Wc1  = (const float*)d_in[16];
    const float* bc1  = (const float*)d_in[17];
    const float* Wo   = (const float*)d_in[18];
    const float* bo   = (const float*)d_in[19];
    float* out = (float*)d_out;

    void *pS0, *pS1, *pSeq, *pGrh, *pP;
    cudaGetSymbolAddress(&pS0,  g_s0);
    cudaGetSymbolAddress(&pS1,  g_s1);
    cudaGetSymbolAddress(&pSeq, g_seq);
    cudaGetSymbolAddress(&pGrh, g_grh);
    cudaGetSymbolAddress(&pP,   g_P);
    float* s0  = (float*)pS0;
    float* s1  = (float*)pS1;
    float* seq = (float*)pSeq;
    float* grh = (float*)pGrh;
    float* P   = (float*)pP;

    k_embed<<<(MB_ * (HID_ / 4) + 255) / 256, 256>>>(emb, tok);
    k_prec<<<dim3(MB_ / 64, HID_ / 64, 3), 128>>>(Wu0, Wr0, Wc0);
    k_h0<<<dim3(B_ / 32, HID_ / 32), 256>>>(vgg, W_in, b_in);

    const dim3 gGates(B_ / 32, (2 * HID_) / 32);   // 4 x 32 = 128 CTAs
    const dim3 gCand (B_ / 32, HID_ / 32);         // 4 x 16 =  64 CTAs
    const size_t plane = (size_t)MB_ * HID_;
    const float* Wu0h = Wu0 + (size_t)HID_ * HID_;  // h-part rows of layer-0 W
    const float* Wr0h = Wr0 + (size_t)HID_ * HID_;
    const float* Wc0h = Wc0 + (size_t)HID_ * HID_;

    for (int t = 0; t < T_; t++) {
        const float* Pu = P + 0 * plane + (size_t)t * B_ * HID_;
        const float* Pr = P + 1 * plane + (size_t)t * B_ * HID_;
        const float* Pc = P + 2 * plane + (size_t)t * B_ * HID_;
        // layer 0: K = 512 (h only; x-part precomputed)
        k_gates<4><<<gGates, 256>>>(s0, s0, HID_, Wu0h, bu0, Wr0h, br0, Pu, Pr, s0);
        k_cand <4><<<gCand, 256>>>(grh, grh, HID_, Wc0h, bc0, Pc, s0, (float*)0);
        // layer 1: K = 1024 ([x=s0 | h=s1])
        k_gates<8><<<gGates, 256>>>(s0, s1, HID_, Wu1, bu1, Wr1, br1, (float*)0, (float*)0, s1);
        k_cand <8><<<gCand, 256>>>(s0, grh, HID_, Wc1, bc1, (float*)0, s1,
                                   seq + (size_t)t * B_ * HID_);
    }

    k_logits<<<dim3(MB_ / 64, (VOC_ + 63) / 64), 128>>>(Wo, bo, out);
    if (out_size >= LOGITS_ELEMS + STATE_ELEMS)
        k_state<<<(B_ * HID_ + 255) / 256, 256>>>(out);
}